// round 15
// baseline (speedup 1.0000x reference)
#include <cuda_runtime.h>
#include <math.h>
#include <stdint.h>

// Lin2d: x <- x @ Mt, 1000 times. Collapsed to one complex multiply by
// w = (c - i*s)^1000 (host double math).
// Streaming kernel: 256-bit global ld/st (sm_103a) WITH evict-first (.cs)
// policy, 2 independent v8 accesses per thread (MLP=2), flat contiguous tiling.

__device__ __forceinline__ void rot8_ldst(const float* p, float* q,
                                          float wr, float wi) {
    unsigned a0, a1, a2, a3, a4, a5, a6, a7;
    asm("ld.global.cs.v8.b32 {%0,%1,%2,%3,%4,%5,%6,%7}, [%8];"
        : "=r"(a0), "=r"(a1), "=r"(a2), "=r"(a3),
          "=r"(a4), "=r"(a5), "=r"(a6), "=r"(a7)
        : "l"(p));

    float x0 = __uint_as_float(a0), y0 = __uint_as_float(a1);
    float x1 = __uint_as_float(a2), y1 = __uint_as_float(a3);
    float x2 = __uint_as_float(a4), y2 = __uint_as_float(a5);
    float x3 = __uint_as_float(a6), y3 = __uint_as_float(a7);

    unsigned b0 = __float_as_uint(fmaf(wr, x0, -wi * y0));
    unsigned b1 = __float_as_uint(fmaf(wi, x0,  wr * y0));
    unsigned b2 = __float_as_uint(fmaf(wr, x1, -wi * y1));
    unsigned b3 = __float_as_uint(fmaf(wi, x1,  wr * y1));
    unsigned b4 = __float_as_uint(fmaf(wr, x2, -wi * y2));
    unsigned b5 = __float_as_uint(fmaf(wi, x2,  wr * y2));
    unsigned b6 = __float_as_uint(fmaf(wr, x3, -wi * y3));
    unsigned b7 = __float_as_uint(fmaf(wi, x3,  wr * y3));

    asm volatile("st.global.cs.v8.b32 [%0], {%1,%2,%3,%4,%5,%6,%7,%8};"
                 :: "l"(q),
                    "r"(b0), "r"(b1), "r"(b2), "r"(b3),
                    "r"(b4), "r"(b5), "r"(b6), "r"(b7)
                 : "memory");
}

__global__ void __launch_bounds__(256)
lin2d_apply_kernel(const float* __restrict__ in,
                   float* __restrict__ out,
                   int n8, float wr, float wi) {
    const int bd = blockDim.x;
    int i0 = blockIdx.x * (bd * 2) + threadIdx.x;   // in units of 8 floats
    int i1 = i0 + bd;

    if (i1 < n8) {
        rot8_ldst(in + (size_t)i0 * 8, out + (size_t)i0 * 8, wr, wi);
        rot8_ldst(in + (size_t)i1 * 8, out + (size_t)i1 * 8, wr, wi);
    } else if (i0 < n8) {
        rot8_ldst(in + (size_t)i0 * 8, out + (size_t)i0 * 8, wr, wi);
    }
}

extern "C" void kernel_launch(void* const* d_in, const int* in_sizes, int n_in,
                              void* d_out, int out_size) {
    const float* x = (const float*)d_in[0];
    float* y = (float*)d_out;
    const int n = in_sizes[0];       // total floats = BATCH*2 = 33,554,432
    const int n8 = n / 8;

    // Host-side constants (pure math at capture time; deterministic).
    const double theta = 3.14159265358979323846 / 100.0;
    const double c = (double)((float)cos(theta));
    const double s = (double)((float)sin(theta));
    const int N = 1000;
    const double r   = hypot(c, s);
    const double phi = atan2(s, c);
    const double mag = pow(r, (double)N);
    // w = (c - i*s)^N = mag * (cos(N*phi) - i*sin(N*phi))
    const float wr = (float)(mag * cos((double)N * phi));
    const float wi = (float)(-mag * sin((double)N * phi));

    const int threads = 256;
    const int per_block = threads * 2;
    const int blocks = (n8 + per_block - 1) / per_block;
    lin2d_apply_kernel<<<blocks, threads>>>(x, y, n8, wr, wi);
}